// round 6
// baseline (speedup 1.0000x reference)
#include <cuda_runtime.h>

#define BB 16
#define CC 256
#define HH 128
#define WW 128
#define HW (HH*WW)      // 16384
#define HW4 (HW/4)      // 4096

#define GROUP 4                 // batches per L2-resident group
#define NGROUP (BB/GROUP)       // 4
#define CSPLIT 8                // channel chunks for reduce parallelism
#define CCHUNK (CC/CSPLIT)      // 32

// Scratch (no allocations allowed)
__device__ float g_part[BB * CSPLIT * 2 * HW];  // 16 MB partial max/sum
__device__ float g_red [BB * 2 * HW];           // combined [B,2,H,W]
__device__ float g_gate[BB * HW];               // gate [B,H,W]

// ---------------------------------------------------------------------------
// Kernel 1: partial channel max+sum over a 32-channel chunk.
// Per group: 4 batches x 8 chunks x 4096 float4-columns = 512 CTAs @ 256.
// ---------------------------------------------------------------------------
__global__ void __launch_bounds__(256) reduce_part_kernel(const float* __restrict__ x,
                                                          int g) {
    int idx  = blockIdx.x * blockDim.x + threadIdx.x;  // 0 .. GROUP*CSPLIT*HW4-1
    int col4 = idx & (HW4 - 1);
    int chnk = (idx >> 12) & (CSPLIT - 1);
    int brel = idx >> 15;                              // / (CSPLIT*HW4)
    int b    = g * GROUP + brel;

    const float4* xb = reinterpret_cast<const float4*>(x)
                       + ((size_t)b * CC + (size_t)chnk * CCHUNK) * HW4 + col4;

    float4 v0 = xb[0];
    float4 mx = v0;
    float4 sm = v0;

    #pragma unroll 8
    for (int c = 1; c < CCHUNK; ++c) {
        float4 v = xb[(size_t)c * HW4];
        mx.x = fmaxf(mx.x, v.x);  mx.y = fmaxf(mx.y, v.y);
        mx.z = fmaxf(mx.z, v.z);  mx.w = fmaxf(mx.w, v.w);
        sm.x += v.x;  sm.y += v.y;  sm.z += v.z;  sm.w += v.w;
    }

    float4* pout = reinterpret_cast<float4*>(g_part)
                   + ((size_t)(b * CSPLIT + chnk) * 2) * HW4 + col4;
    pout[0]   = mx;
    pout[HW4] = sm;
}

// ---------------------------------------------------------------------------
// Kernel 2: combine 8 partials -> g_red (max plane, mean plane). L2-hot, tiny.
// Per group: 4 batches x 4096 columns = 64 CTAs @ 256.
// ---------------------------------------------------------------------------
__global__ void __launch_bounds__(256) combine_kernel(int g) {
    int idx  = blockIdx.x * blockDim.x + threadIdx.x;  // 0 .. GROUP*HW4-1
    int col4 = idx & (HW4 - 1);
    int brel = idx >> 12;
    int b    = g * GROUP + brel;

    const float4* pin = reinterpret_cast<const float4*>(g_part)
                        + ((size_t)b * CSPLIT * 2) * HW4 + col4;

    float4 mx = pin[0];
    float4 sm = pin[HW4];
    #pragma unroll
    for (int s = 1; s < CSPLIT; ++s) {
        float4 m = pin[(size_t)(2 * s) * HW4];
        float4 a = pin[(size_t)(2 * s + 1) * HW4];
        mx.x = fmaxf(mx.x, m.x);  mx.y = fmaxf(mx.y, m.y);
        mx.z = fmaxf(mx.z, m.z);  mx.w = fmaxf(mx.w, m.w);
        sm.x += a.x;  sm.y += a.y;  sm.z += a.z;  sm.w += a.w;
    }

    const float inv = 1.0f / (float)CC;
    float4* rout = reinterpret_cast<float4*>(g_red) + (size_t)b * 2 * HW4 + col4;
    rout[0]   = mx;
    rout[HW4] = make_float4(sm.x * inv, sm.y * inv, sm.z * inv, sm.w * inv);
}

// ---------------------------------------------------------------------------
// Kernel 3: 7x7 conv over [2,H,W] + hsigmoid -> g_gate. L2-hot.
// Per group: 4 batches x 16384 outputs = 256 CTAs @ 256.
// ---------------------------------------------------------------------------
__global__ void __launch_bounds__(256) conv_kernel(const float* __restrict__ w,
                                                   const float* __restrict__ bias,
                                                   int g) {
    __shared__ float sw[98];
    __shared__ float sb;
    if (threadIdx.x < 98) sw[threadIdx.x] = w[threadIdx.x];
    if (threadIdx.x == 0) sb = bias[0];
    __syncthreads();

    int idx = blockIdx.x * blockDim.x + threadIdx.x;   // 0 .. GROUP*HW-1
    int b   = g * GROUP + (idx >> 14);
    int hw  = idx & (HW - 1);
    int h   = hw >> 7;
    int wq  = hw & (WW - 1);

    const float* mp = g_red + (size_t)b * 2 * HW;   // max plane
    const float* ap = mp + HW;                      // avg plane

    float acc = sb;
    #pragma unroll
    for (int kh = 0; kh < 7; ++kh) {
        int hh = h + kh - 3;
        if (hh < 0 || hh >= HH) continue;
        int rowoff = hh * WW;
        #pragma unroll
        for (int kw = 0; kw < 7; ++kw) {
            int ww = wq + kw - 3;
            if (ww < 0 || ww >= WW) continue;
            int off = rowoff + ww;
            acc = fmaf(sw[kh * 7 + kw],      mp[off], acc);
            acc = fmaf(sw[49 + kh * 7 + kw], ap[off], acc);
        }
    }
    g_gate[(size_t)b * HW + hw] = __saturatef((acc + 3.0f) * (1.0f / 6.0f));
}

// ---------------------------------------------------------------------------
// Kernel 4: out = x * gate. x reads should hit L2 (just streamed by reduce).
// __ldcs on x (evict-first after use), __stcs on out (don't pollute L2).
// Per group: 4 x 256 x 4096 float4 = 16384 CTAs @ 256.
// ---------------------------------------------------------------------------
__global__ void __launch_bounds__(256) apply_kernel(const float* __restrict__ x,
                                                    float* __restrict__ out,
                                                    int g) {
    size_t i4  = (size_t)blockIdx.x * blockDim.x + threadIdx.x; // group-local
    int brel   = (int)(i4 >> 20);              // / (CC*HW4)
    int hw4    = (int)(i4 & (HW4 - 1));
    int b      = g * GROUP + brel;
    size_t gi4 = (size_t)g * GROUP * CC * HW4 + i4;

    float4 gt = __ldca(reinterpret_cast<const float4*>(g_gate) + (size_t)b * HW4 + hw4);
    float4 v  = __ldcs(reinterpret_cast<const float4*>(x) + gi4);
    float4 o;
    o.x = v.x * gt.x;  o.y = v.y * gt.y;
    o.z = v.z * gt.z;  o.w = v.w * gt.w;
    __stcs(reinterpret_cast<float4*>(out) + gi4, o);
}

// ---------------------------------------------------------------------------
extern "C" void kernel_launch(void* const* d_in, const int* in_sizes, int n_in,
                              void* d_out, int out_size) {
    const float* x      = (const float*)d_in[0];   // [16,256,128,128]
    const float* conv_w = (const float*)d_in[1];   // [1,2,7,7]
    const float* conv_b = (const float*)d_in[2];   // [1]
    float* out = (float*)d_out;

    for (int g = 0; g < NGROUP; ++g) {
        reduce_part_kernel<<<(GROUP * CSPLIT * HW4) / 256, 256>>>(x, g);
        combine_kernel    <<<(GROUP * HW4) / 256,          256>>>(g);
        conv_kernel       <<<(GROUP * HW) / 256,           256>>>(conv_w, conv_b, g);
        apply_kernel      <<<(GROUP * CC * HW4) / 256,     256>>>(x, out, g);
    }
}

// round 7
// speedup vs baseline: 1.0900x; 1.0900x over previous
#include <cuda_runtime.h>

#define BB 16
#define CC 256
#define HH 128
#define WW 128
#define HW (HH*WW)      // 16384
#define HW4 (HW/4)      // 4096

#define GROUP 4                 // batches per L2-resident group (67 MB)
#define NGROUP (BB/GROUP)       // 4

// Scratch (no allocations allowed)
__device__ float g_red [BB * 2 * HW];           // combined [B,2,H,W]
__device__ float g_gate[BB * HW];               // gate [B,H,W]

// ---------------------------------------------------------------------------
// Kernel 1: channel max + mean, CTA-cooperative, no global partials.
// CTA = 256 threads = 32 float4-columns x 8 channel-groups (32 ch each).
// At fixed channel, one warp reads 32 consecutive float4 = 512 B (coalesced).
// Per group: GROUP * (HW4/32) = 4*128 = 512 CTAs.
// ---------------------------------------------------------------------------
__global__ void __launch_bounds__(256) reduce_kernel(const float* __restrict__ x,
                                                     int g) {
    __shared__ float4 s_mx[8][33];   // padded column to dodge phase conflicts
    __shared__ float4 s_sm[8][33];

    int tid = threadIdx.x;
    int col = tid & 31;              // 0..31  (float4 column within tile)
    int grp = tid >> 5;              // 0..7   (channel group)

    int blk     = blockIdx.x;        // 0 .. GROUP*128-1
    int brel    = blk >> 7;
    int colBase = (blk & 127) * 32;
    int b       = g * GROUP + brel;

    const float4* xb = reinterpret_cast<const float4*>(x)
                       + ((size_t)b * CC + (size_t)grp * 32) * HW4 + colBase + col;

    float4 v0 = xb[0];
    float4 mx = v0;
    float4 sm = v0;

    #pragma unroll 8
    for (int c = 1; c < 32; ++c) {
        float4 v = xb[(size_t)c * HW4];
        mx.x = fmaxf(mx.x, v.x);  mx.y = fmaxf(mx.y, v.y);
        mx.z = fmaxf(mx.z, v.z);  mx.w = fmaxf(mx.w, v.w);
        sm.x += v.x;  sm.y += v.y;  sm.z += v.z;  sm.w += v.w;
    }

    s_mx[grp][col] = mx;
    s_sm[grp][col] = sm;
    __syncthreads();

    if (tid < 32) {
        float4 rmx = s_mx[0][tid];
        float4 rsm = s_sm[0][tid];
        #pragma unroll
        for (int s = 1; s < 8; ++s) {
            float4 m = s_mx[s][tid];
            float4 a = s_sm[s][tid];
            rmx.x = fmaxf(rmx.x, m.x);  rmx.y = fmaxf(rmx.y, m.y);
            rmx.z = fmaxf(rmx.z, m.z);  rmx.w = fmaxf(rmx.w, m.w);
            rsm.x += a.x;  rsm.y += a.y;  rsm.z += a.z;  rsm.w += a.w;
        }
        const float inv = 1.0f / (float)CC;
        float4* rout = reinterpret_cast<float4*>(g_red)
                       + (size_t)b * 2 * HW4 + colBase + tid;
        rout[0]   = rmx;
        rout[HW4] = make_float4(rsm.x * inv, rsm.y * inv, rsm.z * inv, rsm.w * inv);
    }
}

// ---------------------------------------------------------------------------
// Kernel 2: 7x7 conv over [2,H,W] + hsigmoid -> g_gate. L2-hot.
// Per group: 4 batches x 16384 outputs = 256 CTAs @ 256.
// ---------------------------------------------------------------------------
__global__ void __launch_bounds__(256) conv_kernel(const float* __restrict__ w,
                                                   const float* __restrict__ bias,
                                                   int g) {
    __shared__ float sw[98];
    __shared__ float sb;
    if (threadIdx.x < 98) sw[threadIdx.x] = w[threadIdx.x];
    if (threadIdx.x == 0) sb = bias[0];
    __syncthreads();

    int idx = blockIdx.x * blockDim.x + threadIdx.x;   // 0 .. GROUP*HW-1
    int b   = g * GROUP + (idx >> 14);
    int hw  = idx & (HW - 1);
    int h   = hw >> 7;
    int wq  = hw & (WW - 1);

    const float* mp = g_red + (size_t)b * 2 * HW;   // max plane
    const float* ap = mp + HW;                      // avg plane

    float acc = sb;
    #pragma unroll
    for (int kh = 0; kh < 7; ++kh) {
        int hh = h + kh - 3;
        if (hh < 0 || hh >= HH) continue;
        int rowoff = hh * WW;
        #pragma unroll
        for (int kw = 0; kw < 7; ++kw) {
            int ww = wq + kw - 3;
            if (ww < 0 || ww >= WW) continue;
            int off = rowoff + ww;
            acc = fmaf(sw[kh * 7 + kw],      mp[off], acc);
            acc = fmaf(sw[49 + kh * 7 + kw], ap[off], acc);
        }
    }
    g_gate[(size_t)b * HW + hw] = __saturatef((acc + 3.0f) * (1.0f / 6.0f));
}

// ---------------------------------------------------------------------------
// Kernel 3: out = x * gate. x reads mostly hit L2 (just streamed by reduce).
// __ldcs on x (evict-first, last use), __stcs on out (don't pollute L2).
// Per group: 4 x 256 x 4096 float4 = 16384 CTAs @ 256.
// ---------------------------------------------------------------------------
__global__ void __launch_bounds__(256) apply_kernel(const float* __restrict__ x,
                                                    float* __restrict__ out,
                                                    int g) {
    size_t i4  = (size_t)blockIdx.x * blockDim.x + threadIdx.x; // group-local
    int brel   = (int)(i4 >> 20);              // / (CC*HW4)
    int hw4    = (int)(i4 & (HW4 - 1));
    int b      = g * GROUP + brel;
    size_t gi4 = (size_t)g * GROUP * CC * HW4 + i4;

    float4 gt = __ldca(reinterpret_cast<const float4*>(g_gate) + (size_t)b * HW4 + hw4);
    float4 v  = __ldcs(reinterpret_cast<const float4*>(x) + gi4);
    float4 o;
    o.x = v.x * gt.x;  o.y = v.y * gt.y;
    o.z = v.z * gt.z;  o.w = v.w * gt.w;
    __stcs(reinterpret_cast<float4*>(out) + gi4, o);
}

// ---------------------------------------------------------------------------
extern "C" void kernel_launch(void* const* d_in, const int* in_sizes, int n_in,
                              void* d_out, int out_size) {
    const float* x      = (const float*)d_in[0];   // [16,256,128,128]
    const float* conv_w = (const float*)d_in[1];   // [1,2,7,7]
    const float* conv_b = (const float*)d_in[2];   // [1]
    float* out = (float*)d_out;

    for (int g = 0; g < NGROUP; ++g) {
        reduce_kernel<<<GROUP * (HW4 / 32),      256>>>(x, g);
        conv_kernel  <<<(GROUP * HW) / 256,      256>>>(conv_w, conv_b, g);
        apply_kernel <<<(GROUP * CC * HW4) / 256, 256>>>(x, out, g);
    }
}